// round 10
// baseline (speedup 1.0000x reference)
#include <cuda_runtime.h>

#define BATCH   64
#define TSTEPS  1024
#define DIM     512
#define NCTA    128          // 8 b-groups x 16 j-groups
#define NBG     8
#define NJG     16
#define CLUSTER 16           // one b-group per cluster (non-portable size)

#define HSTRIDE 576          // staged row stride: 16 chunks x (32 data + 4 pad)
#define TILEF   (8 * HSTRIDE)
#define PROW    33
#define PSEG    (8 * PROW)

// ---------------- scratch for the L2 fallback path only ---------------------
__device__ float    g_h[2][BATCH * DIM];
__device__ unsigned g_bar[TSTEPS * NBG];

// ---------------- f32x2 packed-FMA helpers (sm_100+) ------------------------
static __device__ __forceinline__ unsigned long long packf2(float lo, float hi) {
    unsigned long long r;
    asm("mov.b64 %0, {%1, %2};" : "=l"(r) : "f"(lo), "f"(hi));
    return r;
}
static __device__ __forceinline__ void unpackf2(unsigned long long v, float& lo, float& hi) {
    asm("mov.b64 {%0, %1}, %2;" : "=f"(lo), "=f"(hi) : "l"(v));
}
static __device__ __forceinline__ unsigned long long fma2(
    unsigned long long a, unsigned long long b, unsigned long long c) {
    unsigned long long d;
    asm("fma.rn.f32x2 %0, %1, %2, %3;" : "=l"(d) : "l"(a), "l"(b), "l"(c));
    return d;
}
static __device__ __forceinline__ unsigned int smem_u32(const void* p) {
    unsigned int a;
    asm("{ .reg .u64 t; cvta.to.shared.u64 t, %1; cvt.u32.u64 %0, t; }"
        : "=r"(a) : "l"(p));
    return a;
}

// Padded staged-tile address (R7 layout): chunk ch at 36*ch floats.
static __device__ __forceinline__ int sw_off(int row, int c4) {
    return row * HSTRIDE + c4 * 4 + (c4 >> 3) * 4;
}

// ---------------------------------------------------------------------------
// Matmul partials (identical to R7): warp w = k-slice 64, lane -> (cg, ks).
// 8 rows x 2 cols over 32 k. 64 LDS.128 (conflict-free) + 256 fma2 per warp.
// ---------------------------------------------------------------------------
static __device__ __forceinline__ void mm_partials(
    const float* __restrict__ sm, const unsigned long long w2[2][16],
    int smoff, int seg, int cg, float* __restrict__ part)
{
    unsigned long long acc[8][2];
#pragma unroll
    for (int r = 0; r < 8; r++) { acc[r][0] = 0ULL; acc[r][1] = 0ULL; }

#pragma unroll
    for (int m = 0; m < 8; m++) {
#pragma unroll
        for (int r = 0; r < 8; r++) {
            ulonglong2 h2 = *(const ulonglong2*)(sm + r * HSTRIDE + smoff + m * 4);
            acc[r][0] = fma2(h2.x, w2[0][2 * m + 0], acc[r][0]);
            acc[r][0] = fma2(h2.y, w2[0][2 * m + 1], acc[r][0]);
            acc[r][1] = fma2(h2.x, w2[1][2 * m + 0], acc[r][1]);
            acc[r][1] = fma2(h2.y, w2[1][2 * m + 1], acc[r][1]);
        }
    }
#pragma unroll
    for (int r = 0; r < 8; r++) {
#pragma unroll
        for (int c = 0; c < 2; c++) {
            float lo, hi;
            unpackf2(acc[r][c], lo, hi);
            part[seg * PSEG + r * PROW + cg * 2 + c] = lo + hi;
        }
    }
}

// ===========================================================================
// PRIMARY: 16-CTA cluster kernel. b-group == cluster; h handoff via DSMEM
// push (st.shared::cluster) + split cluster barrier. h never touches L2.
// Per step: mm_r -> S2 -> reduce/tanh -> push h to 16 CTAs -> arrive ->
// S4 -> stage xs (warp-own) -> mm_x -> wait.
// ===========================================================================
__global__ void __launch_bounds__(256, 1) rnn_cluster_kernel(
    const float* __restrict__ W,
    const float* __restrict__ Wr,
    const float* __restrict__ x,
    const float* __restrict__ bias,
    float* __restrict__ out)
{
    __shared__ float hs[2 * TILEF];          // double-buffered h tile  36 KB
    __shared__ float xs[TILEF];              // x tile                  18 KB
    __shared__ float part_r[16 * PSEG];      // 16.9 KB
    __shared__ float part_x[16 * PSEG];      // 16.9 KB

    const int tid  = threadIdx.x;
    const int w    = tid >> 5;
    const int lane = tid & 31;
    const int cg   = lane >> 1;
    const int ks   = lane & 1;
    const int c    = blockIdx.x;
    const int bg   = c >> 4;                 // cluster id
    const int jg   = c & 15;                 // == cluster rank (contiguous map)
    const int b0   = bg * 8;
    const int j0   = jg * 32;

    const int kb    = w * 64 + ks * 32;
    const int smoff = w * 72 + ks * 36;
    const int seg   = w * 2 + ks;

    unsigned long long wr2[2][16], wx2[2][16];
#pragma unroll
    for (int cc = 0; cc < 2; cc++) {
        const int j = j0 + cg * 2 + cc;
#pragma unroll
        for (int p = 0; p < 16; p++) {
            const int k = kb + 2 * p;
            wr2[cc][p] = packf2(Wr[(size_t)k * DIM + j], Wr[(size_t)(k + 1) * DIM + j]);
            wx2[cc][p] = packf2(W[(size_t)k * DIM + j],  W[(size_t)(k + 1) * DIM + j]);
        }
    }
    const int   rrow = tid >> 5;             // output row (one output/thread)
    const int   rcol = tid & 31;             // output col
    const float bv   = bias[j0 + rcol];

    // warp-chunk staging map (covers chunk p fully: 8 rows x 8 float4)
    const int sr0 = lane >> 3,        sc0 = lane & 7;
    const int sr1 = (lane + 32) >> 3, sc1 = (lane + 32) & 7;

    const unsigned int hs_u32 = smem_u32(hs);
    // this thread's h slot within a tile (same offset in every CTA's hs)
    const unsigned int slot_b = (unsigned)(rrow * HSTRIDE + jg * 36 + rcol) * 4u;

    // ---- prologue: xs <- x[0] (warp-own chunks), mm_x, zero hs[0] ----
    float4 xt[4];
#pragma unroll
    for (int pc = 0; pc < 2; pc++) {
        const int p = w * 2 + pc;
        float4 d0 = __ldg((const float4*)(x + ((size_t)(b0 + sr0) * TSTEPS + 0) * DIM + p * 32) + sc0);
        float4 d1 = __ldg((const float4*)(x + ((size_t)(b0 + sr1) * TSTEPS + 0) * DIM + p * 32) + sc1);
        *(float4*)&xs[sr0 * HSTRIDE + p * 36 + sc0 * 4] = d0;
        *(float4*)&xs[sr1 * HSTRIDE + p * 36 + sc1 * 4] = d1;
        const float4 z = make_float4(0.f, 0.f, 0.f, 0.f);
        *(float4*)&hs[sr0 * HSTRIDE + p * 36 + sc0 * 4] = z;
        *(float4*)&hs[sr1 * HSTRIDE + p * 36 + sc1 * 4] = z;
    }
    __syncwarp();
    mm_partials(xs, wx2, smoff, seg, cg, part_x);
#pragma unroll
    for (int pc = 0; pc < 2; pc++) {         // prefetch x[1]
        const int p = w * 2 + pc;
        xt[pc * 2 + 0] = __ldg((const float4*)(x + ((size_t)(b0 + sr0) * TSTEPS + 1) * DIM + p * 32) + sc0);
        xt[pc * 2 + 1] = __ldg((const float4*)(x + ((size_t)(b0 + sr1) * TSTEPS + 1) * DIM + p * 32) + sc1);
    }
    __syncthreads();
    asm volatile("barrier.cluster.arrive.aligned;" ::: "memory");
    asm volatile("barrier.cluster.wait.aligned;"   ::: "memory");

    for (int t = 0; t < TSTEPS; t++) {
        // ---- 1: recurrence on local hs[t&1] ----
        mm_partials(hs + (t & 1) * TILEF, wr2, smoff, seg, cg, part_r);
        __syncthreads();                     // S2: part_r (and peers' part_x) done

        // ---- 2: reduce + tanh ----
        float s = bv;
#pragma unroll
        for (int s8 = 0; s8 < 16; s8++) s += part_x[s8 * PSEG + rrow * PROW + rcol];
#pragma unroll
        for (int s8 = 0; s8 < 16; s8++) s += part_r[s8 * PSEG + rrow * PROW + rcol];
        float hv = tanhf(s);
        if (t == TSTEPS - 1) {
            out[(b0 + rrow) * DIM + j0 + rcol] = hv;
            return;
        }

        // ---- 3: push h value into all 16 cluster CTAs' hs[(t+1)&1] ----
        {
            const unsigned int laddr =
                hs_u32 + (unsigned)(((t + 1) & 1) * TILEF) * 4u + slot_b;
#pragma unroll
            for (int rk = 0; rk < CLUSTER; rk++) {
                asm volatile(
                    "{\n\t.reg .u32 ra;\n\t"
                    "mapa.shared::cluster.u32 ra, %0, %1;\n\t"
                    "st.shared::cluster.f32 [ra], %2;\n\t}"
                    :: "r"(laddr), "r"(rk), "f"(hv) : "memory");
            }
        }
        asm volatile("barrier.cluster.arrive.aligned;" ::: "memory");  // release
        __syncthreads();                     // S4: reduce reads done -> part_x reuse

        // ---- 4: stage xs <- xt (warp-own), prefetch x[t+2], gemm ----
#pragma unroll
        for (int pc = 0; pc < 2; pc++) {
            const int p = w * 2 + pc;
            *(float4*)&xs[sr0 * HSTRIDE + p * 36 + sc0 * 4] = xt[pc * 2 + 0];
            *(float4*)&xs[sr1 * HSTRIDE + p * 36 + sc1 * 4] = xt[pc * 2 + 1];
        }
        __syncwarp();
        {
            const int tn = (t + 2 < TSTEPS) ? (t + 2) : (TSTEPS - 1);
#pragma unroll
            for (int pc = 0; pc < 2; pc++) {
                const int p = w * 2 + pc;
                xt[pc * 2 + 0] = __ldg((const float4*)(
                    x + ((size_t)(b0 + sr0) * TSTEPS + tn) * DIM + p * 32) + sc0);
                xt[pc * 2 + 1] = __ldg((const float4*)(
                    x + ((size_t)(b0 + sr1) * TSTEPS + tn) * DIM + p * 32) + sc1);
            }
        }
        mm_partials(xs, wx2, smoff, seg, cg, part_x);   // xw for t+1

        // ---- 5: wait (acquire): peers' h pushes visible in local hs ----
        asm volatile("barrier.cluster.wait.aligned;" ::: "memory");
    }
}

// ===========================================================================
// FALLBACK: exact R7 kernel (L2 handoff, per-b-group counter barrier).
// ===========================================================================
__global__ void __launch_bounds__(256, 1) rnn_l2_kernel(
    const float* __restrict__ W,
    const float* __restrict__ Wr,
    const float* __restrict__ x,
    const float* __restrict__ bias,
    float* __restrict__ out)
{
    __shared__ float hs[TILEF];
    __shared__ float xs[TILEF];
    __shared__ float part[16 * PSEG];

    const int tid  = threadIdx.x;
    const int w    = tid >> 5;
    const int lane = tid & 31;
    const int cg   = lane >> 1;
    const int ks   = lane & 1;
    const int c    = blockIdx.x;
    const int b0   = (c >> 4) * 8;
    const int j0   = (c & 15) * 32;
    const int bg   = c >> 4;

    const int kb    = w * 64 + ks * 32;
    const int smoff = w * 72 + ks * 36;
    const int seg   = w * 2 + ks;

    unsigned long long wr2[2][16], wx2[2][16];
#pragma unroll
    for (int cc = 0; cc < 2; cc++) {
        const int j = j0 + cg * 2 + cc;
#pragma unroll
        for (int p = 0; p < 16; p++) {
            const int k = kb + 2 * p;
            wr2[cc][p] = packf2(Wr[(size_t)k * DIM + j], Wr[(size_t)(k + 1) * DIM + j]);
            wx2[cc][p] = packf2(W[(size_t)k * DIM + j],  W[(size_t)(k + 1) * DIM + j]);
        }
    }
    const int   rrow = tid >> 5;
    const int   rcol = tid & 31;
    const float bv   = bias[j0 + rcol];

#pragma unroll
    for (int q = 0; q < 4; q++) {
        int idx = tid + q * 256, row = idx >> 7, c4 = idx & 127;
        *(float4*)&xs[sw_off(row, c4)] =
            __ldg((const float4*)(x + ((size_t)(b0 + row) * TSTEPS + 0) * DIM) + c4);
    }
    __syncthreads();
    mm_partials(xs, wx2, smoff, seg, cg, part);
    __syncthreads();
    float xw_cur = bv;
#pragma unroll
    for (int s8 = 0; s8 < 16; s8++) xw_cur += part[s8 * PSEG + rrow * PROW + rcol];
    __syncthreads();

    for (int t = 0; t < TSTEPS; t++) {
        const float4* hsrc = (const float4*)(g_h[t & 1] + b0 * DIM);
        float4 xt[4];
        const int tn = (t + 1 < TSTEPS) ? (t + 1) : (TSTEPS - 1);
#pragma unroll
        for (int q = 0; q < 4; q++) {
            int idx = tid + q * 256, row = idx >> 7, c4 = idx & 127;
            *(float4*)&hs[sw_off(row, c4)] = __ldcg(hsrc + idx);
            xt[q] = __ldg((const float4*)(
                x + ((size_t)(b0 + row) * TSTEPS + tn) * DIM) + c4);
        }
        __syncthreads();

        mm_partials(hs, wr2, smoff, seg, cg, part);
        __syncthreads();

        float s = xw_cur;
#pragma unroll
        for (int s8 = 0; s8 < 16; s8++) s += part[s8 * PSEG + rrow * PROW + rcol];
        float hv = tanhf(s);
        if (t == TSTEPS - 1) {
            out[(b0 + rrow) * DIM + j0 + rcol] = hv;
            return;
        }
        __stcg(&g_h[(t + 1) & 1][(b0 + rrow) * DIM + j0 + rcol], hv);
        __syncthreads();

        if (tid == 0) {
            unsigned* ctr = &g_bar[t * NBG + bg];
            asm volatile("red.release.gpu.global.add.u32 [%0], %1;"
                         :: "l"(ctr), "r"(1u) : "memory");
        }

#pragma unroll
        for (int q = 0; q < 4; q++) {
            int idx = tid + q * 256, row = idx >> 7, c4 = idx & 127;
            *(float4*)&xs[sw_off(row, c4)] = xt[q];
        }
        __syncthreads();
        mm_partials(xs, wx2, smoff, seg, cg, part);
        __syncthreads();
        float s2 = bv;
#pragma unroll
        for (int s8 = 0; s8 < 16; s8++) s2 += part[s8 * PSEG + rrow * PROW + rcol];
        xw_cur = s2;

        if (tid == 0) {
            const unsigned* ctr = &g_bar[t * NBG + bg];
            unsigned v;
            do {
                asm volatile("ld.acquire.gpu.global.u32 %0, [%1];"
                             : "=r"(v) : "l"(ctr) : "memory");
            } while (v < 16u);
        }
        __syncthreads();
    }
}

// ============================================================================
extern "C" void kernel_launch(void* const* d_in, const int* in_sizes, int n_in,
                              void* d_out, int out_size)
{
    const float* x    = (const float*)d_in[0];
    const float* W    = (const float*)d_in[1];
    const float* Wr   = (const float*)d_in[2];
    const float* bias = (const float*)d_in[3];
    float* out = (float*)d_out;

    // Probe: can this device run 16-CTA clusters for our kernel?
    // (pure host-side query, deterministic, graph-capture safe)
    cudaFuncSetAttribute(rnn_cluster_kernel,
                         cudaFuncAttributeNonPortableClusterSizeAllowed, 1);
    cudaLaunchConfig_t cfg = {};
    cfg.gridDim  = dim3(NCTA, 1, 1);
    cfg.blockDim = dim3(256, 1, 1);
    cfg.dynamicSmemBytes = 0;
    cfg.stream = 0;
    int maxc = 0;
    cudaOccupancyMaxPotentialClusterSize(&maxc, rnn_cluster_kernel, &cfg);

    if (maxc >= CLUSTER) {
        cudaLaunchAttribute attrs[1];
        attrs[0].id = cudaLaunchAttributeClusterDimension;
        attrs[0].val.clusterDim.x = CLUSTER;
        attrs[0].val.clusterDim.y = 1;
        attrs[0].val.clusterDim.z = 1;
        cfg.attrs = attrs;
        cfg.numAttrs = 1;
        cudaLaunchKernelEx(&cfg, rnn_cluster_kernel, W, Wr, x, bias, out);
    } else {
        void* bar_p; cudaGetSymbolAddress(&bar_p, g_bar);
        void* h_p;   cudaGetSymbolAddress(&h_p, g_h);
        cudaMemsetAsync(bar_p, 0, sizeof(unsigned) * TSTEPS * NBG);
        cudaMemsetAsync(h_p, 0, sizeof(float) * BATCH * DIM);
        rnn_l2_kernel<<<NCTA, 256>>>(W, Wr, x, bias, out);
    }
}

// round 11
// speedup vs baseline: 2.0915x; 2.0915x over previous
#include <cuda_runtime.h>

#define BATCH   64
#define TSTEPS  1024
#define DIM     512
#define NCTA    128          // 8 b-groups x 16 j-groups; co-resident
#define NBG     8
#define NJG     16

#define HSTRIDE 576          // staged row stride: 16 chunks x (32 data + 4 pad)
#define TILEF   (8 * HSTRIDE)
#define PROW    33
#define PSEG    (8 * PROW)

// ---------------- scratch (device globals; no allocations) ------------------
// h stored as (value, tag) pairs: tag == t  <=>  this word holds h_t.
// Ping-pong: h_t lives in buffer t&1. Zero-init = (0.0f, tag 0) = valid h_0.
__device__ uint2 g_h2[2][BATCH * DIM];       // 512 KB

// ---------------- f32x2 packed-FMA helpers (sm_100+) ------------------------
static __device__ __forceinline__ unsigned long long packf2(float lo, float hi) {
    unsigned long long r;
    asm("mov.b64 %0, {%1, %2};" : "=l"(r) : "f"(lo), "f"(hi));
    return r;
}
static __device__ __forceinline__ void unpackf2(unsigned long long v, float& lo, float& hi) {
    asm("mov.b64 {%0, %1}, %2;" : "=f"(lo), "=f"(hi) : "l"(v));
}
static __device__ __forceinline__ unsigned long long fma2(
    unsigned long long a, unsigned long long b, unsigned long long c) {
    unsigned long long d;
    asm("fma.rn.f32x2 %0, %1, %2, %3;" : "=l"(d) : "l"(a), "l"(b), "l"(c));
    return d;
}

// L2-coherent raw accessors for the tagged h buffer (no L1, no fences needed:
// the consumer's gate (tag) travels in the same 8B word as the value).
static __device__ __forceinline__ uint4 ldcg_v4(const void* p) {
    uint4 r;
    asm volatile("ld.global.cg.v4.b32 {%0,%1,%2,%3}, [%4];"
                 : "=r"(r.x), "=r"(r.y), "=r"(r.z), "=r"(r.w) : "l"(p));
    return r;
}
static __device__ __forceinline__ void stcg_v2(void* p, unsigned a, unsigned b) {
    asm volatile("st.global.cg.v2.b32 [%0], {%1,%2};"
                 :: "l"(p), "r"(a), "r"(b) : "memory");
}

// Padded staged-tile address (R7 layout): chunk ch at 36*ch floats.
static __device__ __forceinline__ int sw_off(int row, int c4) {
    return row * HSTRIDE + c4 * 4 + (c4 >> 3) * 4;
}

// ---------------------------------------------------------------------------
// Matmul partials (identical to R7): warp w = k-slice 64, lane -> (cg, ks).
// 8 rows x 2 cols over 32 k. 64 LDS.128 (conflict-free) + 256 fma2 per warp.
// ---------------------------------------------------------------------------
static __device__ __forceinline__ void mm_partials(
    const float* __restrict__ sm, const unsigned long long w2[2][16],
    int smoff, int seg, int cg, float* __restrict__ part)
{
    unsigned long long acc[8][2];
#pragma unroll
    for (int r = 0; r < 8; r++) { acc[r][0] = 0ULL; acc[r][1] = 0ULL; }

#pragma unroll
    for (int m = 0; m < 8; m++) {
#pragma unroll
        for (int r = 0; r < 8; r++) {
            ulonglong2 h2 = *(const ulonglong2*)(sm + r * HSTRIDE + smoff + m * 4);
            acc[r][0] = fma2(h2.x, w2[0][2 * m + 0], acc[r][0]);
            acc[r][0] = fma2(h2.y, w2[0][2 * m + 1], acc[r][0]);
            acc[r][1] = fma2(h2.x, w2[1][2 * m + 0], acc[r][1]);
            acc[r][1] = fma2(h2.y, w2[1][2 * m + 1], acc[r][1]);
        }
    }
#pragma unroll
    for (int r = 0; r < 8; r++) {
#pragma unroll
        for (int c = 0; c < 2; c++) {
            float lo, hi;
            unpackf2(acc[r][c], lo, hi);
            part[seg * PSEG + r * PROW + cg * 2 + c] = lo + hi;
        }
    }
}

// ---------------------------------------------------------------------------
// Fused persistent kernel (R7 skeleton, tag-in-data handoff):
//   h_{t+1} = tanh( (x_t@W + b) + h_t@Wr )
// CTA c: rows [b0,b0+8), cols [j0,j0+32). Per step:
//   stage h_t (tagged, retry stale) + prefetch x[t+1] -> S1 -> mm_r -> S2 ->
//   reduce+tanh -> st.cg.v2 (h, t+1) -> S4 -> stage xs -> S5 -> mm_x -> S6.
// No atomics, no flags, no fences: the tag IS the sync.
// ---------------------------------------------------------------------------
__global__ void __launch_bounds__(256, 1) rnn_fused_kernel(
    const float* __restrict__ W,      // [512,512] row-major
    const float* __restrict__ Wr,     // [512,512] row-major
    const float* __restrict__ x,      // [64,1024,512]
    const float* __restrict__ bias,   // [512]
    float* __restrict__ out)          // [64,512]
{
    __shared__ float hs[TILEF];              // staged h tile   18 KB
    __shared__ float xs[TILEF];              // staged x tile   18 KB
    __shared__ float part[16 * PSEG];        // partials        16.9 KB

    const int tid  = threadIdx.x;
    const int w    = tid >> 5;               // warp: k-slice [w*64, +64)
    const int lane = tid & 31;
    const int cg   = lane >> 1;              // col pair
    const int ks   = lane & 1;               // k half
    const int c    = blockIdx.x;
    const int b0   = (c >> 4) * 8;
    const int j0   = (c & 15) * 32;

    const int kb    = w * 64 + ks * 32;
    const int smoff = w * 72 + ks * 36;
    const int seg   = w * 2 + ks;

    // persistent packed weights: (k, k+1) pairs for this thread's 2 columns
    unsigned long long wr2[2][16], wx2[2][16];
#pragma unroll
    for (int cc = 0; cc < 2; cc++) {
        const int j = j0 + cg * 2 + cc;
#pragma unroll
        for (int p = 0; p < 16; p++) {
            const int k = kb + 2 * p;
            wr2[cc][p] = packf2(Wr[(size_t)k * DIM + j], Wr[(size_t)(k + 1) * DIM + j]);
            wx2[cc][p] = packf2(W[(size_t)k * DIM + j],  W[(size_t)(k + 1) * DIM + j]);
        }
    }
    const int   rrow = tid >> 5;             // output row
    const int   rcol = tid & 31;             // output col
    const float bv   = bias[j0 + rcol];

    // this thread's h pair slot (pair index within a buffer)
    uint2* const hslot_w = &g_h2[0][(b0 + rrow) * DIM + j0 + rcol];   // buf 0
    uint2* const hslot_w1 = &g_h2[1][(b0 + rrow) * DIM + j0 + rcol];  // buf 1

    // ---- prologue: xw for t=0 ----
#pragma unroll
    for (int q = 0; q < 4; q++) {
        int idx = tid + q * 256, row = idx >> 7, c4 = idx & 127;
        *(float4*)&xs[sw_off(row, c4)] =
            __ldg((const float4*)(x + ((size_t)(b0 + row) * TSTEPS + 0) * DIM) + c4);
    }
    __syncthreads();
    mm_partials(xs, wx2, smoff, seg, cg, part);
    __syncthreads();
    float xw_cur = bv;
#pragma unroll
    for (int s8 = 0; s8 < 16; s8++) xw_cur += part[s8 * PSEG + rrow * PROW + rcol];
    __syncthreads();

    for (int t = 0; t < TSTEPS; t++) {
        // ---- stage h_t from tagged buffer + prefetch x[t+1] ----
        const char* hb = (const char*)(g_h2[t & 1] + (size_t)b0 * DIM);
        uint4 a[8];
        float4 xt[4];
        const int tn = (t + 1 < TSTEPS) ? (t + 1) : (TSTEPS - 1);
#pragma unroll
        for (int q = 0; q < 4; q++) {
            int idx = tid + q * 256;               // logical float4 in tile
            // pair base = idx*4 pairs -> byte offset idx*32; two 16B halves
            a[2 * q + 0] = ldcg_v4(hb + (size_t)idx * 32);
            a[2 * q + 1] = ldcg_v4(hb + (size_t)idx * 32 + 16);
        }
#pragma unroll
        for (int q = 0; q < 4; q++) {              // x prefetch issued early
            int idx = tid + q * 256, row = idx >> 7, c4 = idx & 127;
            xt[q] = __ldg((const float4*)(
                x + ((size_t)(b0 + row) * TSTEPS + tn) * DIM) + c4);
        }
        // tag check + retry stale vectors (tags in .y/.w; want tag == t)
        {
            const unsigned want = (unsigned)t;
#pragma unroll
            for (int v = 0; v < 8; v++) {
                while ((a[v].y != want) | (a[v].w != want)) {
                    int idx = tid + (v >> 1) * 256;
                    a[v] = ldcg_v4(hb + (size_t)idx * 32 + (v & 1) * 16);
                }
            }
        }
#pragma unroll
        for (int q = 0; q < 4; q++) {
            int idx = tid + q * 256, row = idx >> 7, c4 = idx & 127;
            float4 hv4;
            hv4.x = __uint_as_float(a[2 * q + 0].x);
            hv4.y = __uint_as_float(a[2 * q + 0].z);
            hv4.z = __uint_as_float(a[2 * q + 1].x);
            hv4.w = __uint_as_float(a[2 * q + 1].z);
            *(float4*)&hs[sw_off(row, c4)] = hv4;
        }
        __syncthreads();                     // S1: hs complete

        // ---- recurrence: h_t @ Wr ----
        mm_partials(hs, wr2, smoff, seg, cg, part);
        __syncthreads();                     // S2: part complete

        // ---- reduce + tanh + tagged store ----
        float s = xw_cur;
#pragma unroll
        for (int s8 = 0; s8 < 16; s8++) s += part[s8 * PSEG + rrow * PROW + rcol];
        float hv = tanhf(s);
        if (t == TSTEPS - 1) {
            out[(b0 + rrow) * DIM + j0 + rcol] = hv;
            return;
        }
        stcg_v2(((t + 1) & 1) ? hslot_w1 : hslot_w,
                __float_as_uint(hv), (unsigned)(t + 1));
        __syncthreads();                     // S4: part reads done -> reuse

        // ---- gemm for t+1 fills the store->load window ----
#pragma unroll
        for (int q = 0; q < 4; q++) {
            int idx = tid + q * 256, row = idx >> 7, c4 = idx & 127;
            *(float4*)&xs[sw_off(row, c4)] = xt[q];
        }
        __syncthreads();                     // S5: xs complete
        mm_partials(xs, wx2, smoff, seg, cg, part);
        __syncthreads();                     // S6: part complete
        float s2 = bv;
#pragma unroll
        for (int s8 = 0; s8 < 16; s8++) s2 += part[s8 * PSEG + rrow * PROW + rcol];
        xw_cur = s2;
    }
}

// ============================================================================
extern "C" void kernel_launch(void* const* d_in, const int* in_sizes, int n_in,
                              void* d_out, int out_size)
{
    const float* x    = (const float*)d_in[0];   // [64,1024,512]
    const float* W    = (const float*)d_in[1];   // [512,512]
    const float* Wr   = (const float*)d_in[2];   // [512,512]
    const float* bias = (const float*)d_in[3];   // [512]
    float* out = (float*)d_out;                  // [64,512]

    void* h_p; cudaGetSymbolAddress(&h_p, g_h2);

    // per-launch reset (graph-capturable, replay-safe):
    // zeroed pairs = (h=0.0f, tag=0) = exactly h_0 for t=0 consumers.
    cudaMemsetAsync(h_p, 0, sizeof(uint2) * 2 * BATCH * DIM);

    rnn_fused_kernel<<<NCTA, 256>>>(W, Wr, x, bias, out);
}

// round 13
// speedup vs baseline: 2.1461x; 1.0261x over previous
#include <cuda_runtime.h>

#define BATCH   64
#define TSTEPS  1024
#define DIM     512
#define NCTA    128          // 8 b-groups x 16 j-groups; co-resident
#define NBG     8
#define NJG     16

#define HSTRIDE 576          // staged row stride: 16 chunks x (32 data + 4 pad)
#define TILEF   (8 * HSTRIDE)
#define PROW    33
#define PSEG    (8 * PROW)

// ---------------- scratch (device globals; no allocations) ------------------
// h stored as (value, tag) pairs: tag == t  <=>  this word holds h_t.
// Ping-pong: h_t lives in buffer t&1. Zero-init = (0.0f, tag 0) = valid h_0.
__device__ uint2 g_h2[2][BATCH * DIM];       // 512 KB

// ---------------- f32x2 packed-FMA helpers (sm_100+) ------------------------
static __device__ __forceinline__ unsigned long long packf2(float lo, float hi) {
    unsigned long long r;
    asm("mov.b64 %0, {%1, %2};" : "=l"(r) : "f"(lo), "f"(hi));
    return r;
}
static __device__ __forceinline__ void unpackf2(unsigned long long v, float& lo, float& hi) {
    asm("mov.b64 {%0, %1}, %2;" : "=f"(lo), "=f"(hi) : "l"(v));
}
static __device__ __forceinline__ unsigned long long fma2(
    unsigned long long a, unsigned long long b, unsigned long long c) {
    unsigned long long d;
    asm("fma.rn.f32x2 %0, %1, %2, %3;" : "=l"(d) : "l"(a), "l"(b), "l"(c));
    return d;
}

// L2-coherent raw accessors for the tagged h buffer (the consumer's gate (tag)
// travels in the same 16B load as the values -> no fences, no atomics).
static __device__ __forceinline__ uint4 ldcg_v4(const void* p) {
    uint4 r;
    asm volatile("ld.global.cg.v4.b32 {%0,%1,%2,%3}, [%4];"
                 : "=r"(r.x), "=r"(r.y), "=r"(r.z), "=r"(r.w) : "l"(p));
    return r;
}
static __device__ __forceinline__ void stcg_v2(void* p, unsigned a, unsigned b) {
    asm volatile("st.global.cg.v2.b32 [%0], {%1,%2};"
                 :: "l"(p), "r"(a), "r"(b) : "memory");
}

// Padded staged-tile address: chunk ch at 36*ch floats (conflict-free LDS.128).
static __device__ __forceinline__ int sw_off(int row, int c4) {
    return row * HSTRIDE + c4 * 4 + (c4 >> 3) * 4;
}

// ---------------------------------------------------------------------------
// Matmul partials: warp w = k-slice 64, lane -> (cg: col pair, ks: k half).
// 8 rows x 2 cols over 32 k. 64 LDS.128 (conflict-free) + 256 fma2 per warp.
// Reads ONLY chunks 2w, 2w+1 of the staged tile.
// ---------------------------------------------------------------------------
static __device__ __forceinline__ void mm_partials(
    const float* __restrict__ sm, const unsigned long long w2[2][16],
    int smoff, int seg, int cg, float* __restrict__ part)
{
    unsigned long long acc[8][2];
#pragma unroll
    for (int r = 0; r < 8; r++) { acc[r][0] = 0ULL; acc[r][1] = 0ULL; }

#pragma unroll
    for (int m = 0; m < 8; m++) {
#pragma unroll
        for (int r = 0; r < 8; r++) {
            ulonglong2 h2 = *(const ulonglong2*)(sm + r * HSTRIDE + smoff + m * 4);
            acc[r][0] = fma2(h2.x, w2[0][2 * m + 0], acc[r][0]);
            acc[r][0] = fma2(h2.y, w2[0][2 * m + 1], acc[r][0]);
            acc[r][1] = fma2(h2.x, w2[1][2 * m + 0], acc[r][1]);
            acc[r][1] = fma2(h2.y, w2[1][2 * m + 1], acc[r][1]);
        }
    }
#pragma unroll
    for (int r = 0; r < 8; r++) {
#pragma unroll
        for (int c = 0; c < 2; c++) {
            float lo, hi;
            unpackf2(acc[r][c], lo, hi);
            part[seg * PSEG + r * PROW + cg * 2 + c] = lo + hi;
        }
    }
}

// ---------------------------------------------------------------------------
// Fused persistent kernel (R11 spine, S5 deleted):
//   h_{t+1} = tanh( (x_t@W + b) + h_t@Wr )
// CTA c: rows [b0,b0+8), cols [j0,j0+32). Per step (4 CTA barriers):
//   stage h_t (tagged, CTA-wide) + prefetch x[t+1] (warp-chunk regs) -> S1 ->
//   mm_r -> part -> S2 -> reduce (xw_cur + part) + tanh + tagged stcg -> S4 ->
//   stage xs (warp-own, syncwarp) -> mm_x -> part -> S6 -> reduce2 -> xw_cur.
// Single part buffer; xw_cur carried in a register (proven R11 hazard set).
// ---------------------------------------------------------------------------
__global__ void __launch_bounds__(256, 1) rnn_fused_kernel(
    const float* __restrict__ W,      // [512,512] row-major
    const float* __restrict__ Wr,     // [512,512] row-major
    const float* __restrict__ x,      // [64,1024,512]
    const float* __restrict__ bias,   // [512]
    float* __restrict__ out)          // [64,512]
{
    __shared__ float hs[TILEF];              // staged h tile   18 KB
    __shared__ float xs[TILEF];              // staged x tile   18 KB
    __shared__ float part[16 * PSEG];        // partials        16.9 KB

    const int tid  = threadIdx.x;
    const int w    = tid >> 5;               // warp: k-slice [w*64, +64)
    const int lane = tid & 31;
    const int cg   = lane >> 1;              // col pair
    const int ks   = lane & 1;               // k half
    const int c    = blockIdx.x;
    const int b0   = (c >> 4) * 8;
    const int j0   = (c & 15) * 32;

    const int kb    = w * 64 + ks * 32;
    const int smoff = w * 72 + ks * 36;
    const int seg   = w * 2 + ks;

    // persistent packed weights: (k, k+1) pairs for this thread's 2 columns
    unsigned long long wr2[2][16], wx2[2][16];
#pragma unroll
    for (int cc = 0; cc < 2; cc++) {
        const int j = j0 + cg * 2 + cc;
#pragma unroll
        for (int p = 0; p < 16; p++) {
            const int k = kb + 2 * p;
            wr2[cc][p] = packf2(Wr[(size_t)k * DIM + j], Wr[(size_t)(k + 1) * DIM + j]);
            wx2[cc][p] = packf2(W[(size_t)k * DIM + j],  W[(size_t)(k + 1) * DIM + j]);
        }
    }
    const int   rrow = tid >> 5;             // output row
    const int   rcol = tid & 31;             // output col
    const float bv   = bias[j0 + rcol];

    // this thread's tagged h slots (one per ping-pong buffer)
    uint2* const hslot0 = &g_h2[0][(b0 + rrow) * DIM + j0 + rcol];
    uint2* const hslot1 = &g_h2[1][(b0 + rrow) * DIM + j0 + rcol];

    // warp-chunk map for x prefetch / xs staging: float4 v -> (row, col4)
    const int sr0 = lane >> 3,        sc0 = lane & 7;         // v = lane
    const int sr1 = (lane + 32) >> 3, sc1 = (lane + 32) & 7;  // v = lane+32

    // ---- prologue: xs <- x[0] (warp-own chunks), mm_x, xw_cur for t=0 ----
    float4 xt[4];
#pragma unroll
    for (int pc = 0; pc < 2; pc++) {
        const int p = w * 2 + pc;
        float4 d0 = __ldg((const float4*)(x + ((size_t)(b0 + sr0) * TSTEPS + 0) * DIM + p * 32) + sc0);
        float4 d1 = __ldg((const float4*)(x + ((size_t)(b0 + sr1) * TSTEPS + 0) * DIM + p * 32) + sc1);
        *(float4*)&xs[sr0 * HSTRIDE + p * 36 + sc0 * 4] = d0;
        *(float4*)&xs[sr1 * HSTRIDE + p * 36 + sc1 * 4] = d1;
    }
    __syncwarp();
    mm_partials(xs, wx2, smoff, seg, cg, part);
    __syncthreads();
    float xw_cur = bv;
#pragma unroll
    for (int s8 = 0; s8 < 16; s8++) xw_cur += part[s8 * PSEG + rrow * PROW + rcol];
    __syncthreads();                         // guard part reuse by mm_r(0)

    for (int t = 0; t < TSTEPS; t++) {
        // ---- stage h_t (tagged, CTA-wide) + prefetch x[t+1] (warp-chunk) ----
        const char* hb = (const char*)(g_h2[t & 1] + (size_t)b0 * DIM);
        uint4 a[8];
#pragma unroll
        for (int q = 0; q < 4; q++) {
            int idx = tid + q * 256;               // logical float4 in tile
            a[2 * q + 0] = ldcg_v4(hb + (size_t)idx * 32);
            a[2 * q + 1] = ldcg_v4(hb + (size_t)idx * 32 + 16);
        }
        {
            const int tn = (t + 1 < TSTEPS) ? (t + 1) : (TSTEPS - 1);
#pragma unroll
            for (int pc = 0; pc < 2; pc++) {
                const int p = w * 2 + pc;
                xt[pc * 2 + 0] = __ldg((const float4*)(
                    x + ((size_t)(b0 + sr0) * TSTEPS + tn) * DIM + p * 32) + sc0);
                xt[pc * 2 + 1] = __ldg((const float4*)(
                    x + ((size_t)(b0 + sr1) * TSTEPS + tn) * DIM + p * 32) + sc1);
            }
        }
        // tag check + retry stale vectors (tags in .y/.w; want tag == t)
        {
            const unsigned want = (unsigned)t;
#pragma unroll
            for (int v = 0; v < 8; v++) {
                while ((a[v].y != want) | (a[v].w != want)) {
                    int idx = tid + (v >> 1) * 256;
                    a[v] = ldcg_v4(hb + (size_t)idx * 32 + (v & 1) * 16);
                }
            }
        }
#pragma unroll
        for (int q = 0; q < 4; q++) {
            int idx = tid + q * 256, row = idx >> 7, c4 = idx & 127;
            float4 hv4;
            hv4.x = __uint_as_float(a[2 * q + 0].x);
            hv4.y = __uint_as_float(a[2 * q + 0].z);
            hv4.z = __uint_as_float(a[2 * q + 1].x);
            hv4.w = __uint_as_float(a[2 * q + 1].z);
            *(float4*)&hs[sw_off(row, c4)] = hv4;
        }
        __syncthreads();                     // S1: hs complete

        // ---- recurrence: h_t @ Wr -> part ----
        mm_partials(hs, wr2, smoff, seg, cg, part);
        __syncthreads();                     // S2: part complete

        // ---- reduce + tanh + tagged store ----
        float s = xw_cur;
#pragma unroll
        for (int s8 = 0; s8 < 16; s8++) s += part[s8 * PSEG + rrow * PROW + rcol];
        float hv = tanhf(s);
        if (t == TSTEPS - 1) {
            out[(b0 + rrow) * DIM + j0 + rcol] = hv;
            return;
        }
        stcg_v2(((t + 1) & 1) ? hslot1 : hslot0,
                __float_as_uint(hv), (unsigned)(t + 1));
        __syncthreads();                     // S4: part reads done -> reuse

        // ---- stage xs (warp-own chunks from regs) + mm_x -> part ----
#pragma unroll
        for (int pc = 0; pc < 2; pc++) {
            const int p = w * 2 + pc;
            *(float4*)&xs[sr0 * HSTRIDE + p * 36 + sc0 * 4] = xt[pc * 2 + 0];
            *(float4*)&xs[sr1 * HSTRIDE + p * 36 + sc1 * 4] = xt[pc * 2 + 1];
        }
        __syncwarp();
        mm_partials(xs, wx2, smoff, seg, cg, part);
        __syncthreads();                     // S6: part complete
        float s2 = bv;
#pragma unroll
        for (int s8 = 0; s8 < 16; s8++) s2 += part[s8 * PSEG + rrow * PROW + rcol];
        xw_cur = s2;
        // (no barrier needed before next S1: no warp passes S1(t+1) until all
        //  finish reduce2 reads; mm_r(t+1) writes part only after S1(t+1))
    }
}

// ============================================================================
extern "C" void kernel_launch(void* const* d_in, const int* in_sizes, int n_in,
                              void* d_out, int out_size)
{
    const float* x    = (const float*)d_in[0];   // [64,1024,512]
    const float* W    = (const float*)d_in[1];   // [512,512]
    const float* Wr   = (const float*)d_in[2];   // [512,512]
    const float* bias = (const float*)d_in[3];   // [512]
    float* out = (float*)d_out;                  // [64,512]

    void* h_p; cudaGetSymbolAddress(&h_p, g_h2);

    // per-launch reset (graph-capturable, replay-safe):
    // zeroed pairs = (h=0.0f, tag=0) = exactly h_0 for t=0 consumers.
    cudaMemsetAsync(h_p, 0, sizeof(uint2) * 2 * BATCH * DIM);

    rnn_fused_kernel<<<NCTA, 256>>>(W, Wr, x, bias, out);
}